// round 1
// baseline (speedup 1.0000x reference)
#include <cuda_runtime.h>
#include <math.h>

#define IMGSZ 224
#define HW (IMGSZ*IMGSZ)     // 50176
#define NK 100
#define NP 16
#define NB 8

// ---------------- device scratch (static, no runtime alloc) ----------------
__device__ float g_A[NP*IMGSZ];                   // resize matrix [16,224]
__device__ float g_centers[NB][NK][5];            // SLIC centers
__device__ unsigned char g_labels[NB][HW];        // per-pixel labels
__device__ float g_tmp[NB][NK][NP][IMGSZ][3];     // row-resized masked tiles (34.4 MB)

__device__ __forceinline__ float slic_ratio() {
    // COMPACT / S, S = sqrt(H*W/K); matches numpy double math then fp32 cast
    return (float)(10.0 / sqrt(224.0 * 224.0 / 100.0));
}

// ---------------- init: resize matrix + center init ----------------
__global__ void k_init(const float* __restrict__ x) {
    int b = blockIdx.x;
    int t = threadIdx.x;

    // A: computed by block 0, threads 0..15 (one output row each)
    if (b == 0 && t < NP) {
        float sample = (t + 0.5f) * 14.0f - 0.5f;
        float total = 0.0f;
        for (int h = 0; h < IMGSZ; h++) {
            float d = fabsf(sample - (float)h) * (1.0f / 14.0f);
            float w = fmaxf(0.0f, 1.0f - d);
            g_A[t * IMGSZ + h] = w;
            total += w;
        }
        float inv = 1.0f / total;
        for (int h = 0; h < IMGSZ; h++) g_A[t * IMGSZ + h] *= inv;
    }

    // centers: threads 0..99 per image block
    if (t < NK) {
        // int((i+0.5)*224/10) with numpy's ((i+0.5)*224)/10 evaluation order
        const int cg[10] = {11, 33, 56, 78, 100, 123, 145, 168, 190, 212};
        int gy = t / 10, gx = t % 10;
        int h = cg[gy], w = cg[gx];
        const float* im = x + (size_t)b * 3 * HW;
        float ratio = slic_ratio();
        g_centers[b][t][0] = im[0 * HW + h * IMGSZ + w];
        g_centers[b][t][1] = im[1 * HW + h * IMGSZ + w];
        g_centers[b][t][2] = im[2 * HW + h * IMGSZ + w];
        g_centers[b][t][3] = (float)h * ratio;
        g_centers[b][t][4] = (float)w * ratio;
    }
}

// ---------------- assignment: nearest center per pixel ----------------
#define PXT 4   // pixels per thread
__global__ __launch_bounds__(256) void k_assign(const float* __restrict__ x) {
    __shared__ float sc[NK][5];
    __shared__ float sc2[NK];
    int b = blockIdx.y;
    int t = threadIdx.x;

    if (t < NK) {
        float c0 = g_centers[b][t][0];
        float c1 = g_centers[b][t][1];
        float c2 = g_centers[b][t][2];
        float c3 = g_centers[b][t][3];
        float c4 = g_centers[b][t][4];
        sc[t][0] = c0; sc[t][1] = c1; sc[t][2] = c2; sc[t][3] = c3; sc[t][4] = c4;
        sc2[t] = c0*c0 + c1*c1 + c2*c2 + c3*c3 + c4*c4;
    }
    __syncthreads();

    const float* im = x + (size_t)b * 3 * HW;
    const float ratio = slic_ratio();
    int base = blockIdx.x * (blockDim.x * PXT);

#pragma unroll
    for (int j = 0; j < PXT; j++) {
        int i = base + j * 256 + t;       // grid sized so i < HW always
        int h = i / IMGSZ, w = i - h * IMGSZ;
        float f0 = im[i];
        float f1 = im[HW + i];
        float f2 = im[2 * HW + i];
        float f3 = (float)h * ratio;
        float f4 = (float)w * ratio;
        float fsq = f0*f0 + f1*f1 + f2*f2 + f3*f3 + f4*f4;

        float best = 3.4e38f;
        int bi = 0;
#pragma unroll 4
        for (int k = 0; k < NK; k++) {
            float dot = f0 * sc[k][0];
            dot = fmaf(f1, sc[k][1], dot);
            dot = fmaf(f2, sc[k][2], dot);
            dot = fmaf(f3, sc[k][3], dot);
            dot = fmaf(f4, sc[k][4], dot);
            float d = fsq + sc2[k] - 2.0f * dot;
            if (d < best) { best = d; bi = k; }   // strict < => first-min tie-break
        }
        g_labels[b][i] = (unsigned char)bi;
    }
}

// ---------------- center update: deterministic double reduction ----------------
__global__ __launch_bounds__(256) void k_update(const float* __restrict__ x) {
    int b = blockIdx.y;
    int k = blockIdx.x;
    int t = threadIdx.x;
    const unsigned char* lbl = g_labels[b];
    const float* im = x + (size_t)b * 3 * HW;
    const float ratio = slic_ratio();

    double s0 = 0, s1 = 0, s2 = 0, s3 = 0, s4 = 0, cnt = 0;
    for (int i = t; i < HW; i += 256) {
        if (lbl[i] == (unsigned char)k) {
            int h = i / IMGSZ, w = i - h * IMGSZ;
            s0 += (double)im[i];
            s1 += (double)im[HW + i];
            s2 += (double)im[2 * HW + i];
            s3 += (double)((float)h * ratio);
            s4 += (double)((float)w * ratio);
            cnt += 1.0;
        }
    }
    // warp reduce
#pragma unroll
    for (int off = 16; off > 0; off >>= 1) {
        s0 += __shfl_down_sync(0xffffffffu, s0, off);
        s1 += __shfl_down_sync(0xffffffffu, s1, off);
        s2 += __shfl_down_sync(0xffffffffu, s2, off);
        s3 += __shfl_down_sync(0xffffffffu, s3, off);
        s4 += __shfl_down_sync(0xffffffffu, s4, off);
        cnt += __shfl_down_sync(0xffffffffu, cnt, off);
    }
    __shared__ double red[8][6];
    int warp = t >> 5, lane = t & 31;
    if (lane == 0) {
        red[warp][0] = s0; red[warp][1] = s1; red[warp][2] = s2;
        red[warp][3] = s3; red[warp][4] = s4; red[warp][5] = cnt;
    }
    __syncthreads();
    if (t == 0) {
        double a0 = 0, a1 = 0, a2 = 0, a3 = 0, a4 = 0, ac = 0;
#pragma unroll
        for (int w2 = 0; w2 < 8; w2++) {
            a0 += red[w2][0]; a1 += red[w2][1]; a2 += red[w2][2];
            a3 += red[w2][3]; a4 += red[w2][4]; ac += red[w2][5];
        }
        if (ac > 0.0) {
            g_centers[b][k][0] = (float)(a0 / ac);
            g_centers[b][k][1] = (float)(a1 / ac);
            g_centers[b][k][2] = (float)(a2 / ac);
            g_centers[b][k][3] = (float)(a3 / ac);
            g_centers[b][k][4] = (float)(a4 / ac);
        }
        // cnt == 0: keep old center (matches jnp.where)
    }
}

// ---------------- zero the tmp scratch ----------------
__global__ void k_zero_tmp() {
    size_t n4 = (size_t)NB * NK * NP * IMGSZ * 3 / 4;   // 2,150,400 float4s
    size_t i = (size_t)blockIdx.x * blockDim.x + threadIdx.x;
    if (i < n4) reinterpret_cast<float4*>(g_tmp)[i] = make_float4(0.f, 0.f, 0.f, 0.f);
}

// ---------------- stage 1: row-resize masked image (scatter by label) ----------------
__global__ __launch_bounds__(256) void k_stage1(const float* __restrict__ x) {
    int b = blockIdx.y;
    int i = blockIdx.x * blockDim.x + threadIdx.x;
    if (i >= HW) return;
    int h = i / IMGSZ, w = i - h * IMGSZ;
    int k = g_labels[b][i];
    const float* im = x + (size_t)b * 3 * HW;
    float r = im[i], g = im[HW + i], bl = im[2 * HW + i];

    int q0 = max(0, (int)ceilf((h - 20.5f) * (1.0f / 14.0f)));
    int q1 = min(NP - 1, (int)floorf((h + 7.5f) * (1.0f / 14.0f)));
    for (int q = q0; q <= q1; q++) {
        float wt = g_A[q * IMGSZ + h];
        if (wt != 0.0f) {
            float* dst = &g_tmp[b][k][q][w][0];
            atomicAdd(dst + 0, wt * r);
            atomicAdd(dst + 1, wt * g);
            atomicAdd(dst + 2, wt * bl);
        }
    }
}

// ---------------- stage 2: column-resize + output permutation ----------------
__global__ __launch_bounds__(64) void k_stage2(float* __restrict__ out) {
    int b = blockIdx.y;
    int kp = blockIdx.x;             // k*16 + p
    int k = kp >> 4, p = kp & 15;
    __shared__ float srow[IMGSZ * 3];
    int t = threadIdx.x;
    const float* tp = &g_tmp[b][k][p][0][0];
    for (int j = t; j < IMGSZ * 3; j += 64) srow[j] = tp[j];
    __syncthreads();
    if (t < 48) {
        int q = t / 3, c = t - q * 3;
        const float* Aq = &g_A[q * IMGSZ];
        float acc = 0.0f;
#pragma unroll 8
        for (int w = 0; w < IMGSZ; w++) acc = fmaf(Aq[w], srow[w * 3 + c], acc);
        // sp[b,k,p,q,c] -> reshape(B, K*C, P*P) -> transpose -> out[b, s, kc]
        int lin = ((k * 16 + p) * 16 + q) * 3 + c;
        int kc = lin >> 8;           // / 256
        int s  = lin & 255;          // % 256
        out[((size_t)b * 256 + s) * 300 + kc] = acc;
    }
}

// ---------------- launch ----------------
extern "C" void kernel_launch(void* const* d_in, const int* in_sizes, int n_in,
                              void* d_out, int out_size) {
    const float* x = (const float*)d_in[0];
    float* out = (float*)d_out;

    k_init<<<NB, 128>>>(x);

    dim3 ga(HW / (256 * PXT), NB);      // 49 x 8
    dim3 gu(NK, NB);                    // 100 x 8
    for (int it = 0; it < 10; it++) {
        k_assign<<<ga, 256>>>(x);
        k_update<<<gu, 256>>>(x);
    }
    k_assign<<<ga, 256>>>(x);           // final labels

    size_t n4 = (size_t)NB * NK * NP * IMGSZ * 3 / 4;
    k_zero_tmp<<<(unsigned)((n4 + 255) / 256), 256>>>();

    dim3 g1((HW + 255) / 256, NB);      // 196 x 8
    k_stage1<<<g1, 256>>>(x);

    dim3 g2(NK * NP, NB);               // 1600 x 8
    k_stage2<<<g2, 64>>>(out);
}